// round 12
// baseline (speedup 1.0000x reference)
#include <cuda_runtime.h>
#include <cuda_fp16.h>

// ---------------- problem constants ----------------
#define NMAX 50000
#define EMAX 800000
#define MKER 27            // 3^3 spline kernels
#define C    64            // hidden channels
#define YSTR (MKER * C)    // 1728 halves per node
#define SSTR 108           // 27 * 4 (ci0,ci1,ci2,pad) layer-0 agg row

// ---------------- static scratch ----------------
__device__ __half g_y[(size_t)NMAX * YSTR];   // 172.8 MB transformed features (fp16)
__device__ float  g_root[NMAX * C];           // fp32 root-weight term h @ Wr
__device__ float  g_h[NMAX * C];              // hidden state (fp32)
__device__ float  g_S[NMAX * SSTR];           // layer-0 input-space agg (21.6 MB)
__device__ float4 g_rec[EMAX];                // CSR edge records: (src, ea0, ea1, ea2)
__device__ int    g_rowptr[NMAX + 1];
__device__ int    g_cursor[NMAX];
__device__ int    g_deg[NMAX];

// ---------------- helpers ----------------
__device__ __forceinline__ float2 ffma2(float2 a, float2 b, float2 c) {
    float2 d;
    asm("fma.rn.f32x2 %0, %1, %2, %3;"
        : "=l"(*reinterpret_cast<unsigned long long*>(&d))
        : "l"(*reinterpret_cast<unsigned long long*>(&a)),
          "l"(*reinterpret_cast<unsigned long long*>(&b)),
          "l"(*reinterpret_cast<unsigned long long*>(&c)));
    return d;
}

__device__ __forceinline__ void basis8(float e0, float e1, float e2,
                                       float w[8], int kk[8]) {
    float p0 = e0 * 2.0f, p1 = e1 * 2.0f, p2 = e2 * 2.0f;
    float f0 = fminf(fmaxf(floorf(p0), 0.f), 1.f);
    float f1 = fminf(fmaxf(floorf(p1), 0.f), 1.f);
    float f2 = fminf(fmaxf(floorf(p2), 0.f), 1.f);
    float u0 = p0 - f0, u1 = p1 - f1, u2 = p2 - f2;
    int base = (int)f0 + 3 * (int)f1 + 9 * (int)f2;
#pragma unroll
    for (int b = 0; b < 8; b++) {
        float a0 = (b & 1) ? u0 : 1.f - u0;
        float a1 = (b & 2) ? u1 : 1.f - u1;
        float a2 = (b & 4) ? u2 : 1.f - u2;
        w[b]  = a0 * a1 * a2;
        kk[b] = base + (b & 1) + 3 * ((b >> 1) & 1) + 9 * ((b >> 2) & 1);
    }
}

// ---------------- CSR build ----------------
__global__ void zeroAll_kernel(int N) {
    int i = blockIdx.x * blockDim.x + threadIdx.x;
    if (i < N * SSTR) g_S[i] = 0.f;
    if (i < N)        g_deg[i] = 0;
}
__global__ void hist_kernel(const int* __restrict__ dst, int E) {
    int i = blockIdx.x * blockDim.x + threadIdx.x;
    if (i < E) atomicAdd(&g_deg[dst[i]], 1);
}
// single-block exclusive scan of g_deg -> g_rowptr (and g_cursor copy)
__global__ void scan_kernel(int N) {
    __shared__ int ssum[1024];
    int tid = threadIdx.x;
    int chunk = (N + 1023) / 1024;
    int beg = tid * chunk;
    int end = min(beg + chunk, N);
    int s = 0;
    for (int i = beg; i < end; i++) s += g_deg[i];
    ssum[tid] = s;
    __syncthreads();
    for (int off = 1; off < 1024; off <<= 1) {
        int v = 0;
        if (tid >= off) v = ssum[tid - off];
        __syncthreads();
        if (tid >= off) ssum[tid] += v;
        __syncthreads();
    }
    int run = (tid == 0) ? 0 : ssum[tid - 1];
    for (int i = beg; i < end; i++) {
        g_rowptr[i] = run;
        g_cursor[i] = run;
        run += g_deg[i];
    }
    if (tid == 1023) g_rowptr[N] = ssum[1023];
}

// edge pass: write CSR record + layer-0 input-space scatter (float4 RED)
__global__ void build_kernel(const int* __restrict__ src,
                             const int* __restrict__ dst,
                             const float* __restrict__ ea,
                             const float* __restrict__ x, int E) {
    int e = blockIdx.x * blockDim.x + threadIdx.x;
    if (e >= E) return;
    int s = src[e], d = dst[e];
    float e0 = ea[3 * e], e1 = ea[3 * e + 1], e2 = ea[3 * e + 2];

    int pos = atomicAdd(&g_cursor[d], 1);
    g_rec[pos] = make_float4(__int_as_float(s), e0, e1, e2);

    float w[8]; int kk[8];
    basis8(e0, e1, e2, w, kk);
    float x0 = __ldg(x + 3 * s), x1 = __ldg(x + 3 * s + 1), x2 = __ldg(x + 3 * s + 2);
    float4* Sb = (float4*)(g_S + (size_t)d * SSTR);
#pragma unroll
    for (int c = 0; c < 8; c++)
        atomicAdd(Sb + kk[c], make_float4(w[c] * x0, w[c] * x1, w[c] * x2, 0.f));
}

// ---------------- layer 0 finalize: h = relu(S@W0/deg + x@root0 + b0) --------
__global__ void __launch_bounds__(256)
l0_kernel(const float* __restrict__ x, const float* __restrict__ W0,
          const float* __restrict__ root0, const float* __restrict__ b0, int N) {
    int n    = (blockIdx.x * blockDim.x + threadIdx.x) >> 5;
    int lane = threadIdx.x & 31;
    if (n >= N) return;
    const float* Sr = g_S + (size_t)n * SSTR;
    float sA = Sr[lane];
    float sB = Sr[32 + lane];
    float sC = Sr[64 + lane];
    float sD = (lane < 12) ? Sr[96 + lane] : 0.f;

    float2 acc = make_float2(0.f, 0.f);
#pragma unroll
    for (int m = 0; m < MKER; m++) {
#pragma unroll
        for (int ci = 0; ci < 3; ci++) {
            int s  = m * 4 + ci;
            int r  = s >> 5, sl = s & 31;
            float v = (r == 0) ? __shfl_sync(0xffffffffu, sA, sl)
                    : (r == 1) ? __shfl_sync(0xffffffffu, sB, sl)
                    : (r == 2) ? __shfl_sync(0xffffffffu, sC, sl)
                               : __shfl_sync(0xffffffffu, sD, sl);
            float2 wv = __ldg((const float2*)(W0 + (m * 3 + ci) * C) + lane);
            acc.x += v * wv.x;
            acc.y += v * wv.y;
        }
    }
    int   dg  = g_rowptr[n + 1] - g_rowptr[n];
    float inv = 1.f / (float)(dg > 0 ? dg : 1);
    float xv  = (lane < 3) ? __ldg(x + 3 * n + lane) : 0.f;
    float x0  = __shfl_sync(0xffffffffu, xv, 0);
    float x1  = __shfl_sync(0xffffffffu, xv, 1);
    float x2  = __shfl_sync(0xffffffffu, xv, 2);
    float2 r0 = __ldg((const float2*)(root0)         + lane);
    float2 r1 = __ldg((const float2*)(root0 + C)     + lane);
    float2 r2 = __ldg((const float2*)(root0 + 2 * C) + lane);
    float2 bb = __ldg((const float2*)(b0)            + lane);
    float2 res;
    res.x = fmaxf(acc.x * inv + x0 * r0.x + x1 * r1.x + x2 * r2.x + bb.x, 0.f);
    res.y = fmaxf(acc.y * inv + x0 * r0.y + x1 * r1.y + x2 * r2.y + bb.y, 0.f);
    ((float2*)g_h)[(size_t)n * 32 + lane] = res;
}

// ---------------- transform (R10 conflict-free orientation) ------------------
#define T_NODES 64
#define HT_STR  68
__global__ void __launch_bounds__(256)
transform_kernel(const float* __restrict__ h, const float* __restrict__ W,
                 const float* __restrict__ Wr, int N) {
    __shared__ float Wt[C * C];        // [ci][co] natural
    __shared__ float hsT[C * HT_STR];  // [ci][n] padded
    int m   = blockIdx.y;
    int n0  = blockIdx.x * T_NODES;
    int tid = threadIdx.x;

    const float* Wm = (m < MKER) ? (W + m * C * C) : Wr;
    for (int i = tid; i < C * C; i += 256)
        Wt[i] = Wm[i];
    for (int i = tid; i < T_NODES * C; i += 256) {
        int nl = i >> 6, ci = i & 63;
        int n  = n0 + nl;
        hsT[ci * HT_STR + nl] = (n < N) ? h[(size_t)n * C + ci] : 0.f;
    }
    __syncthreads();

    int co = tid & 63;
    int nb = (tid >> 6) * 16;

    float2 acc[8];
#pragma unroll
    for (int j = 0; j < 8; j++) acc[j] = make_float2(0.f, 0.f);

#pragma unroll 8
    for (int ci = 0; ci < C; ci++) {
        float  w  = Wt[ci * C + co];
        float2 wd = make_float2(w, w);
        const float4* hp = (const float4*)&hsT[ci * HT_STR + nb];
        float4 a = hp[0], b = hp[1], c = hp[2], d = hp[3];
        acc[0] = ffma2(make_float2(a.x, a.y), wd, acc[0]);
        acc[1] = ffma2(make_float2(a.z, a.w), wd, acc[1]);
        acc[2] = ffma2(make_float2(b.x, b.y), wd, acc[2]);
        acc[3] = ffma2(make_float2(b.z, b.w), wd, acc[3]);
        acc[4] = ffma2(make_float2(c.x, c.y), wd, acc[4]);
        acc[5] = ffma2(make_float2(c.z, c.w), wd, acc[5]);
        acc[6] = ffma2(make_float2(d.x, d.y), wd, acc[6]);
        acc[7] = ffma2(make_float2(d.z, d.w), wd, acc[7]);
    }

#pragma unroll
    for (int j = 0; j < 8; j++) {
        int n = n0 + nb + 2 * j;
        if (n >= N) break;
        if (m < MKER) {
            g_y[(size_t)n * YSTR + m * C + co] = __float2half_rn(acc[j].x);
            if (n + 1 < N)
                g_y[(size_t)(n + 1) * YSTR + m * C + co] = __float2half_rn(acc[j].y);
        } else {
            g_root[(size_t)n * C + co] = acc[j].x;
            if (n + 1 < N)
                g_root[(size_t)(n + 1) * C + co] = acc[j].y;
        }
    }
}

// ---------------- node kernel (layers 1,2): warp per dst node ----------------
// IDEMPOTENT: reads g_y/g_root/g_rec/rowptr, writes only h_out (never reads it).
// This round launches it TWICE per layer: the timing delta vs R10 = 2*G,
// pinning the transform/gather split that the data so far leave degenerate.
__global__ void __launch_bounds__(256)
node_kernel(const float* __restrict__ bias, float* __restrict__ h_out, int N) {
    __shared__ float4 recs[8][32];
    int wid  = threadIdx.x >> 5;
    int lane = threadIdx.x & 31;
    int n    = (blockIdx.x * blockDim.x + threadIdx.x) >> 5;
    if (n >= N) return;
    int beg = g_rowptr[n], end = g_rowptr[n + 1];

    float2 acc = make_float2(0.f, 0.f);
    for (int base = beg; base < end; base += 32) {
        int cnt = min(32, end - base);
        __syncwarp();
        if (lane < cnt) recs[wid][lane] = __ldg(&g_rec[base + lane]);
        __syncwarp();
#pragma unroll 4
        for (int e = 0; e < cnt; e++) {
            float4 r = recs[wid][e];                 // LDS broadcast
            int s = __float_as_int(r.x);
            float w[8]; int kk[8];
            basis8(r.y, r.z, r.w, w, kk);
            const __half* yb = g_y + (size_t)s * YSTR;
#pragma unroll
            for (int c = 0; c < 8; c++) {
                __half2 hv = __ldg((const __half2*)(yb + kk[c] * C) + lane);
                float2 v = __half22float2(hv);
                acc.x += w[c] * v.x;
                acc.y += w[c] * v.y;
            }
        }
    }
    int   dg  = end - beg;
    float inv = 1.f / (float)(dg > 0 ? dg : 1);
    float2 rt = __ldg((const float2*)(g_root + (size_t)n * C) + lane);
    float2 bb = __ldg((const float2*)bias + lane);
    float2 res;
    res.x = fmaxf(acc.x * inv + rt.x + bb.x, 0.f);
    res.y = fmaxf(acc.y * inv + rt.y + bb.y, 0.f);
    ((float2*)h_out)[(size_t)n * 32 + lane] = res;
}

// ---------------- launch ----------------
extern "C" void kernel_launch(void* const* d_in, const int* in_sizes, int n_in,
                              void* d_out, int out_size) {
    const float* x     = (const float*)d_in[0];
    const int*   ei    = (const int*)d_in[1];
    const float* ea    = (const float*)d_in[2];
    const float* W0    = (const float*)d_in[3];
    const float* root0 = (const float*)d_in[4];
    const float* b0    = (const float*)d_in[5];
    const float* W1    = (const float*)d_in[6];
    const float* root1 = (const float*)d_in[7];
    const float* b1    = (const float*)d_in[8];
    const float* W2    = (const float*)d_in[9];
    const float* root2 = (const float*)d_in[10];
    const float* b2    = (const float*)d_in[11];
    float* out = (float*)d_out;

    int N = in_sizes[0] / 3;
    int E = in_sizes[1] / 2;
    const int* src = ei;
    const int* dst = ei + E;

    float* hP;
    cudaGetSymbolAddress((void**)&hP, g_h);

    int nodeBlocks = (N * 32 + 255) / 256;
    dim3 tGrid((N + T_NODES - 1) / T_NODES, MKER + 1);

    // ---- CSR + layer-0 scatter ----
    zeroAll_kernel<<<(N * SSTR + 255) / 256, 256>>>(N);
    hist_kernel<<<(E + 255) / 256, 256>>>(dst, E);
    scan_kernel<<<1, 1024>>>(N);
    build_kernel<<<(E + 255) / 256, 256>>>(src, dst, ea, x, E);

    // ---- layer 0 ----
    l0_kernel<<<nodeBlocks, 256>>>(x, W0, root0, b0, N);

    // ---- layer 1 (node_kernel duplicated: measurement, bit-identical) ----
    transform_kernel<<<tGrid, 256>>>(hP, W1, root1, N);
    node_kernel<<<nodeBlocks, 256>>>(b1, hP, N);
    node_kernel<<<nodeBlocks, 256>>>(b1, hP, N);

    // ---- layer 2 (node_kernel duplicated: measurement, bit-identical) ----
    transform_kernel<<<tGrid, 256>>>(hP, W2, root2, N);
    node_kernel<<<nodeBlocks, 256>>>(b2, out, N);
    node_kernel<<<nodeBlocks, 256>>>(b2, out, N);
}

// round 13
// speedup vs baseline: 2.3028x; 2.3028x over previous
#include <cuda_runtime.h>
#include <cuda_fp16.h>
#include <mma.h>

using namespace nvcuda;

// ---------------- problem constants ----------------
#define NMAX 50000
#define EMAX 800000
#define MKER 27            // 3^3 spline kernels
#define C    64            // hidden channels
#define YSTR (MKER * C)    // 1728 halves per node
#define SSTR 108           // 27 * 4 (ci0,ci1,ci2,pad) layer-0 agg row

// ---------------- static scratch ----------------
__device__ __half g_y[(size_t)NMAX * YSTR];   // 172.8 MB transformed features (fp16)
__device__ __half g_hh[NMAX * C];             // hidden state (fp16)
__device__ __half g_w16[28 * C * C];          // fp16 weights [m][ci][co] (27 spline + root)
__device__ float  g_root[NMAX * C];           // fp32 root-weight term h @ Wr
__device__ float  g_S[NMAX * SSTR];           // layer-0 input-space agg (21.6 MB)
__device__ float4 g_rec[EMAX];                // CSR edge records: (src, ea0, ea1, ea2)
__device__ int    g_rowptr[NMAX + 1];
__device__ int    g_cursor[NMAX];
__device__ int    g_deg[NMAX];

// ---------------- basis helpers ----------------
__device__ __forceinline__ void basis8(float e0, float e1, float e2,
                                       float w[8], int kk[8]) {
    float p0 = e0 * 2.0f, p1 = e1 * 2.0f, p2 = e2 * 2.0f;
    float f0 = fminf(fmaxf(floorf(p0), 0.f), 1.f);
    float f1 = fminf(fmaxf(floorf(p1), 0.f), 1.f);
    float f2 = fminf(fmaxf(floorf(p2), 0.f), 1.f);
    float u0 = p0 - f0, u1 = p1 - f1, u2 = p2 - f2;
    int base = (int)f0 + 3 * (int)f1 + 9 * (int)f2;
#pragma unroll
    for (int b = 0; b < 8; b++) {
        float a0 = (b & 1) ? u0 : 1.f - u0;
        float a1 = (b & 2) ? u1 : 1.f - u1;
        float a2 = (b & 4) ? u2 : 1.f - u2;
        w[b]  = a0 * a1 * a2;
        kk[b] = base + (b & 1) + 3 * ((b >> 1) & 1) + 9 * ((b >> 2) & 1);
    }
}

// ---------------- CSR build ----------------
__global__ void zeroAll_kernel(int N) {
    int i = blockIdx.x * blockDim.x + threadIdx.x;
    if (i < N * SSTR) g_S[i] = 0.f;
    if (i < N)        g_deg[i] = 0;
}
__global__ void hist_kernel(const int* __restrict__ dst, int E) {
    int i = blockIdx.x * blockDim.x + threadIdx.x;
    if (i < E) atomicAdd(&g_deg[dst[i]], 1);
}
__global__ void scan_kernel(int N) {
    __shared__ int ssum[1024];
    int tid = threadIdx.x;
    int chunk = (N + 1023) / 1024;
    int beg = tid * chunk;
    int end = min(beg + chunk, N);
    int s = 0;
    for (int i = beg; i < end; i++) s += g_deg[i];
    ssum[tid] = s;
    __syncthreads();
    for (int off = 1; off < 1024; off <<= 1) {
        int v = 0;
        if (tid >= off) v = ssum[tid - off];
        __syncthreads();
        if (tid >= off) ssum[tid] += v;
        __syncthreads();
    }
    int run = (tid == 0) ? 0 : ssum[tid - 1];
    for (int i = beg; i < end; i++) {
        g_rowptr[i] = run;
        g_cursor[i] = run;
        run += g_deg[i];
    }
    if (tid == 1023) g_rowptr[N] = ssum[1023];
}

__global__ void build_kernel(const int* __restrict__ src,
                             const int* __restrict__ dst,
                             const float* __restrict__ ea,
                             const float* __restrict__ x, int E) {
    int e = blockIdx.x * blockDim.x + threadIdx.x;
    if (e >= E) return;
    int s = src[e], d = dst[e];
    float e0 = ea[3 * e], e1 = ea[3 * e + 1], e2 = ea[3 * e + 2];

    int pos = atomicAdd(&g_cursor[d], 1);
    g_rec[pos] = make_float4(__int_as_float(s), e0, e1, e2);

    float w[8]; int kk[8];
    basis8(e0, e1, e2, w, kk);
    float x0 = __ldg(x + 3 * s), x1 = __ldg(x + 3 * s + 1), x2 = __ldg(x + 3 * s + 2);
    float4* Sb = (float4*)(g_S + (size_t)d * SSTR);
#pragma unroll
    for (int c = 0; c < 8; c++)
        atomicAdd(Sb + kk[c], make_float4(w[c] * x0, w[c] * x1, w[c] * x2, 0.f));
}

// ---------------- layer 0 finalize: h = relu(S@W0/deg + x@root0 + b0) --------
__global__ void __launch_bounds__(256)
l0_kernel(const float* __restrict__ x, const float* __restrict__ W0,
          const float* __restrict__ root0, const float* __restrict__ b0, int N) {
    int n    = (blockIdx.x * blockDim.x + threadIdx.x) >> 5;
    int lane = threadIdx.x & 31;
    if (n >= N) return;
    const float* Sr = g_S + (size_t)n * SSTR;
    float sA = Sr[lane];
    float sB = Sr[32 + lane];
    float sC = Sr[64 + lane];
    float sD = (lane < 12) ? Sr[96 + lane] : 0.f;

    float2 acc = make_float2(0.f, 0.f);
#pragma unroll
    for (int m = 0; m < MKER; m++) {
#pragma unroll
        for (int ci = 0; ci < 3; ci++) {
            int s  = m * 4 + ci;
            int r  = s >> 5, sl = s & 31;
            float v = (r == 0) ? __shfl_sync(0xffffffffu, sA, sl)
                    : (r == 1) ? __shfl_sync(0xffffffffu, sB, sl)
                    : (r == 2) ? __shfl_sync(0xffffffffu, sC, sl)
                               : __shfl_sync(0xffffffffu, sD, sl);
            float2 wv = __ldg((const float2*)(W0 + (m * 3 + ci) * C) + lane);
            acc.x += v * wv.x;
            acc.y += v * wv.y;
        }
    }
    int   dg  = g_rowptr[n + 1] - g_rowptr[n];
    float inv = 1.f / (float)(dg > 0 ? dg : 1);
    float xv  = (lane < 3) ? __ldg(x + 3 * n + lane) : 0.f;
    float x0  = __shfl_sync(0xffffffffu, xv, 0);
    float x1  = __shfl_sync(0xffffffffu, xv, 1);
    float x2  = __shfl_sync(0xffffffffu, xv, 2);
    float2 r0 = __ldg((const float2*)(root0)         + lane);
    float2 r1 = __ldg((const float2*)(root0 + C)     + lane);
    float2 r2 = __ldg((const float2*)(root0 + 2 * C) + lane);
    float2 bb = __ldg((const float2*)(b0)            + lane);
    float v0 = fmaxf(acc.x * inv + x0 * r0.x + x1 * r1.x + x2 * r2.x + bb.x, 0.f);
    float v1 = fmaxf(acc.y * inv + x0 * r0.y + x1 * r1.y + x2 * r2.y + bb.y, 0.f);
    ((__half2*)g_hh)[(size_t)n * 32 + lane] = __floats2half2_rn(v0, v1);
}

// ---------------- W prep: g_w16[m][ci][co] = fp16(W / Wr) --------------------
__global__ void wprep_kernel(const float* __restrict__ W,
                             const float* __restrict__ Wr) {
    int i = blockIdx.x * blockDim.x + threadIdx.x;
    if (i >= 28 * C * C) return;
    int m = i >> 12, r = i & 4095;
    float v = (m < MKER) ? __ldg(W + (size_t)m * C * C + r) : __ldg(Wr + r);
    g_w16[i] = __float2half_rn(v);
}

// ---------------- transform via WMMA (HMMA, fp16 in / fp32 acc) --------------
// Block: 256 threads, 64-node tile x one m-plane. 8 warps, each owns a
// 16x32 C-subtile (4 k-steps x 2 col-frags). m==27 writes fp32 g_root.
#define WM_NODES 64
#define HLD (C + 8)     // half smem leading dim (72; multiple of 8)
__global__ void __launch_bounds__(256)
transform_wmma_kernel(int N) {
    __shared__ __half hs[WM_NODES * HLD];   // [n][ci]   9216 B
    __shared__ __half ws[C * HLD];          // [ci][co]  9216 B
    __shared__ float  outs[WM_NODES * C];   // [n][co]  16384 B
    int m   = blockIdx.y;
    int n0  = blockIdx.x * WM_NODES;
    int tid = threadIdx.x;

    // load h tile (fp16, 8 halves per uint4; 8 uint4 per row)
    for (int i = tid; i < WM_NODES * 8; i += 256) {
        int n = i >> 3, q = i & 7;
        uint4 v = make_uint4(0u, 0u, 0u, 0u);
        if (n0 + n < N)
            v = __ldg((const uint4*)(g_hh + (size_t)(n0 + n) * C) + q);
        *(uint4*)&hs[n * HLD + q * 8] = v;
    }
    // load W plane (fp16)
    for (int i = tid; i < C * 8; i += 256) {
        int ci = i >> 3, q = i & 7;
        uint4 v = __ldg((const uint4*)(g_w16 + (size_t)m * C * C + ci * C) + q);
        *(uint4*)&ws[ci * HLD + q * 8] = v;
    }
    __syncthreads();

    int wid  = tid >> 5;
    int rowb = (wid >> 1) * 16;     // 0,16,32,48
    int colb = (wid & 1) * 32;      // 0,32

    wmma::fragment<wmma::accumulator, 16, 16, 16, float> cf0, cf1;
    wmma::fill_fragment(cf0, 0.f);
    wmma::fill_fragment(cf1, 0.f);
#pragma unroll
    for (int k = 0; k < 4; k++) {
        wmma::fragment<wmma::matrix_a, 16, 16, 16, __half, wmma::row_major> af;
        wmma::load_matrix_sync(af, &hs[rowb * HLD + k * 16], HLD);
        wmma::fragment<wmma::matrix_b, 16, 16, 16, __half, wmma::row_major> bf0, bf1;
        wmma::load_matrix_sync(bf0, &ws[(k * 16) * HLD + colb], HLD);
        wmma::load_matrix_sync(bf1, &ws[(k * 16) * HLD + colb + 16], HLD);
        wmma::mma_sync(cf0, af, bf0, cf0);
        wmma::mma_sync(cf1, af, bf1, cf1);
    }
    wmma::store_matrix_sync(&outs[rowb * C + colb],      cf0, C, wmma::mem_row_major);
    wmma::store_matrix_sync(&outs[rowb * C + colb + 16], cf1, C, wmma::mem_row_major);
    __syncthreads();

    // write out: thread t -> node t>>2, 16 channels at (t&3)*16
    int n = tid >> 2, cq = (tid & 3) * 16;
    if (n0 + n < N) {
        const float* row = &outs[n * C + cq];
        if (m < MKER) {
            __half2 buf[8];
#pragma unroll
            for (int j = 0; j < 8; j++)
                buf[j] = __floats2half2_rn(row[2 * j], row[2 * j + 1]);
            uint4* dst = (uint4*)(g_y + (size_t)(n0 + n) * YSTR + m * C + cq);
            dst[0] = *(uint4*)&buf[0];
            dst[1] = *(uint4*)&buf[4];
        } else {
            float4* dst = (float4*)(g_root + (size_t)(n0 + n) * C + cq);
#pragma unroll
            for (int j = 0; j < 4; j++)
                dst[j] = *(const float4*)&row[4 * j];
        }
    }
}

// ---------------- node kernel (layers 1,2): warp per dst node ----------------
__global__ void __launch_bounds__(256)
node_kernel(const float* __restrict__ bias, float* __restrict__ out32,
            int N, int writeFloat) {
    __shared__ float4 recs[8][32];
    int wid  = threadIdx.x >> 5;
    int lane = threadIdx.x & 31;
    int n    = (blockIdx.x * blockDim.x + threadIdx.x) >> 5;
    if (n >= N) return;
    int beg = g_rowptr[n], end = g_rowptr[n + 1];

    float2 acc = make_float2(0.f, 0.f);
    for (int base = beg; base < end; base += 32) {
        int cnt = min(32, end - base);
        __syncwarp();
        if (lane < cnt) recs[wid][lane] = __ldg(&g_rec[base + lane]);
        __syncwarp();
#pragma unroll 4
        for (int e = 0; e < cnt; e++) {
            float4 r = recs[wid][e];                 // LDS broadcast
            int s = __float_as_int(r.x);
            float w[8]; int kk[8];
            basis8(r.y, r.z, r.w, w, kk);
            const __half* yb = g_y + (size_t)s * YSTR;
#pragma unroll
            for (int c = 0; c < 8; c++) {
                __half2 hv = __ldg((const __half2*)(yb + kk[c] * C) + lane);
                float2 v = __half22float2(hv);
                acc.x += w[c] * v.x;
                acc.y += w[c] * v.y;
            }
        }
    }
    int   dg  = end - beg;
    float inv = 1.f / (float)(dg > 0 ? dg : 1);
    float2 rt = __ldg((const float2*)(g_root + (size_t)n * C) + lane);
    float2 bb = __ldg((const float2*)bias + lane);
    float v0 = fmaxf(acc.x * inv + rt.x + bb.x, 0.f);
    float v1 = fmaxf(acc.y * inv + rt.y + bb.y, 0.f);
    if (writeFloat) {
        ((float2*)out32)[(size_t)n * 32 + lane] = make_float2(v0, v1);
    } else {
        ((__half2*)g_hh)[(size_t)n * 32 + lane] = __floats2half2_rn(v0, v1);
    }
}

// ---------------- launch ----------------
extern "C" void kernel_launch(void* const* d_in, const int* in_sizes, int n_in,
                              void* d_out, int out_size) {
    const float* x     = (const float*)d_in[0];
    const int*   ei    = (const int*)d_in[1];
    const float* ea    = (const float*)d_in[2];
    const float* W0    = (const float*)d_in[3];
    const float* root0 = (const float*)d_in[4];
    const float* b0    = (const float*)d_in[5];
    const float* W1    = (const float*)d_in[6];
    const float* root1 = (const float*)d_in[7];
    const float* b1    = (const float*)d_in[8];
    const float* W2    = (const float*)d_in[9];
    const float* root2 = (const float*)d_in[10];
    const float* b2    = (const float*)d_in[11];
    float* out = (float*)d_out;

    int N = in_sizes[0] / 3;
    int E = in_sizes[1] / 2;
    const int* src = ei;
    const int* dst = ei + E;

    int nodeBlocks = (N * 32 + 255) / 256;
    dim3 tGrid((N + WM_NODES - 1) / WM_NODES, 28);
    int wpBlocks = (28 * C * C + 255) / 256;

    // ---- CSR + layer-0 scatter ----
    zeroAll_kernel<<<(N * SSTR + 255) / 256, 256>>>(N);
    hist_kernel<<<(E + 255) / 256, 256>>>(dst, E);
    scan_kernel<<<1, 1024>>>(N);
    build_kernel<<<(E + 255) / 256, 256>>>(src, dst, ea, x, E);

    // ---- layer 0 ----
    l0_kernel<<<nodeBlocks, 256>>>(x, W0, root0, b0, N);

    // ---- layer 1 ----
    wprep_kernel<<<wpBlocks, 256>>>(W1, root1);
    transform_wmma_kernel<<<tGrid, 256>>>(N);
    node_kernel<<<nodeBlocks, 256>>>(b1, nullptr, N, 0);

    // ---- layer 2 ----
    wprep_kernel<<<wpBlocks, 256>>>(W2, root2);
    transform_wmma_kernel<<<tGrid, 256>>>(N);
    node_kernel<<<nodeBlocks, 256>>>(b2, out, N, 1);
}

// round 15
// speedup vs baseline: 2.3433x; 1.0176x over previous
#include <cuda_runtime.h>
#include <cuda_fp16.h>
#include <mma.h>

using namespace nvcuda;

// ---------------- problem constants ----------------
#define NMAX 50000
#define EMAX 800000
#define MKER 27            // 3^3 spline kernels
#define C    64            // hidden channels
#define YSTR (MKER * C)    // 1728 halves per node
#define SSTR 108           // 27 * 4 (ci0,ci1,ci2,pad) layer-0 agg row
#define WSZ  (28 * C * C)  // 114688 halves per layer of prepped weights

// ---------------- static scratch ----------------
__device__ __half g_y[(size_t)NMAX * YSTR];   // 172.8 MB transformed features (fp16)
__device__ __half g_hh[NMAX * C];             // hidden state (fp16)
__device__ __half g_w16[2 * WSZ];             // fp16 weights [layer][m][ci][co]
__device__ float  g_root[NMAX * C];           // fp32 root-weight term h @ Wr
__device__ float  g_S[NMAX * SSTR];           // layer-0 input-space agg (21.6 MB)
__device__ float4 g_rec[EMAX];                // CSR edge records: (src, ea0, ea1, ea2)
__device__ int    g_rowptr[NMAX + 1];
__device__ int    g_cursor[NMAX];
__device__ int    g_deg[NMAX];

// ---------------- basis helpers ----------------
__device__ __forceinline__ void basis8(float e0, float e1, float e2,
                                       float w[8], int kk[8]) {
    float p0 = e0 * 2.0f, p1 = e1 * 2.0f, p2 = e2 * 2.0f;
    float f0 = fminf(fmaxf(floorf(p0), 0.f), 1.f);
    float f1 = fminf(fmaxf(floorf(p1), 0.f), 1.f);
    float f2 = fminf(fmaxf(floorf(p2), 0.f), 1.f);
    float u0 = p0 - f0, u1 = p1 - f1, u2 = p2 - f2;
    int base = (int)f0 + 3 * (int)f1 + 9 * (int)f2;
#pragma unroll
    for (int b = 0; b < 8; b++) {
        float a0 = (b & 1) ? u0 : 1.f - u0;
        float a1 = (b & 2) ? u1 : 1.f - u1;
        float a2 = (b & 4) ? u2 : 1.f - u2;
        w[b]  = a0 * a1 * a2;
        kk[b] = base + (b & 1) + 3 * ((b >> 1) & 1) + 9 * ((b >> 2) & 1);
    }
}

// ---------------- CSR build ----------------
__global__ void zeroAll_kernel(int N) {
    int i = blockIdx.x * blockDim.x + threadIdx.x;
    if (i < N * SSTR) g_S[i] = 0.f;
    if (i < N)        g_deg[i] = 0;
}
__global__ void hist_kernel(const int* __restrict__ dst, int E) {
    int i = blockIdx.x * blockDim.x + threadIdx.x;
    if (i < E) atomicAdd(&g_deg[dst[i]], 1);
}
__global__ void scan_kernel(int N) {
    __shared__ int ssum[1024];
    int tid = threadIdx.x;
    int chunk = (N + 1023) / 1024;
    int beg = tid * chunk;
    int end = min(beg + chunk, N);
    int s = 0;
    for (int i = beg; i < end; i++) s += g_deg[i];
    ssum[tid] = s;
    __syncthreads();
    for (int off = 1; off < 1024; off <<= 1) {
        int v = 0;
        if (tid >= off) v = ssum[tid - off];
        __syncthreads();
        if (tid >= off) ssum[tid] += v;
        __syncthreads();
    }
    int run = (tid == 0) ? 0 : ssum[tid - 1];
    for (int i = beg; i < end; i++) {
        g_rowptr[i] = run;
        g_cursor[i] = run;
        run += g_deg[i];
    }
    if (tid == 1023) g_rowptr[N] = ssum[1023];
}

__global__ void build_kernel(const int* __restrict__ src,
                             const int* __restrict__ dst,
                             const float* __restrict__ ea,
                             const float* __restrict__ x, int E) {
    int e = blockIdx.x * blockDim.x + threadIdx.x;
    if (e >= E) return;
    int s = src[e], d = dst[e];
    float e0 = ea[3 * e], e1 = ea[3 * e + 1], e2 = ea[3 * e + 2];

    int pos = atomicAdd(&g_cursor[d], 1);
    g_rec[pos] = make_float4(__int_as_float(s), e0, e1, e2);

    float w[8]; int kk[8];
    basis8(e0, e1, e2, w, kk);
    float x0 = __ldg(x + 3 * s), x1 = __ldg(x + 3 * s + 1), x2 = __ldg(x + 3 * s + 2);
    float4* Sb = (float4*)(g_S + (size_t)d * SSTR);
#pragma unroll
    for (int c = 0; c < 8; c++)
        atomicAdd(Sb + kk[c], make_float4(w[c] * x0, w[c] * x1, w[c] * x2, 0.f));
}

// ---------------- layer 0 finalize: h = relu(S@W0/deg + x@root0 + b0) --------
__global__ void __launch_bounds__(256)
l0_kernel(const float* __restrict__ x, const float* __restrict__ W0,
          const float* __restrict__ root0, const float* __restrict__ b0, int N) {
    int n    = (blockIdx.x * blockDim.x + threadIdx.x) >> 5;
    int lane = threadIdx.x & 31;
    if (n >= N) return;
    const float* Sr = g_S + (size_t)n * SSTR;
    float sA = Sr[lane];
    float sB = Sr[32 + lane];
    float sC = Sr[64 + lane];
    float sD = (lane < 12) ? Sr[96 + lane] : 0.f;

    float2 acc = make_float2(0.f, 0.f);
#pragma unroll
    for (int m = 0; m < MKER; m++) {
#pragma unroll
        for (int ci = 0; ci < 3; ci++) {
            int s  = m * 4 + ci;
            int r  = s >> 5, sl = s & 31;
            float v = (r == 0) ? __shfl_sync(0xffffffffu, sA, sl)
                    : (r == 1) ? __shfl_sync(0xffffffffu, sB, sl)
                    : (r == 2) ? __shfl_sync(0xffffffffu, sC, sl)
                               : __shfl_sync(0xffffffffu, sD, sl);
            float2 wv = __ldg((const float2*)(W0 + (m * 3 + ci) * C) + lane);
            acc.x += v * wv.x;
            acc.y += v * wv.y;
        }
    }
    int   dg  = g_rowptr[n + 1] - g_rowptr[n];
    float inv = 1.f / (float)(dg > 0 ? dg : 1);
    float xv  = (lane < 3) ? __ldg(x + 3 * n + lane) : 0.f;
    float x0  = __shfl_sync(0xffffffffu, xv, 0);
    float x1  = __shfl_sync(0xffffffffu, xv, 1);
    float x2  = __shfl_sync(0xffffffffu, xv, 2);
    float2 r0 = __ldg((const float2*)(root0)         + lane);
    float2 r1 = __ldg((const float2*)(root0 + C)     + lane);
    float2 r2 = __ldg((const float2*)(root0 + 2 * C) + lane);
    float2 bb = __ldg((const float2*)(b0)            + lane);
    float v0 = fmaxf(acc.x * inv + x0 * r0.x + x1 * r1.x + x2 * r2.x + bb.x, 0.f);
    float v1 = fmaxf(acc.y * inv + x0 * r0.y + x1 * r1.y + x2 * r2.y + bb.y, 0.f);
    ((__half2*)g_hh)[(size_t)n * 32 + lane] = __floats2half2_rn(v0, v1);
}

// ---------------- W prep (both layers at once): g_w16[l][m][ci][co] ----------
__global__ void wprep_kernel(const float* __restrict__ W1,
                             const float* __restrict__ Wr1,
                             const float* __restrict__ W2,
                             const float* __restrict__ Wr2) {
    int i = blockIdx.x * blockDim.x + threadIdx.x;
    if (i >= 2 * WSZ) return;
    int l   = i / WSZ;                   // FIXED (was i >> 16: WSZ = 114688)
    int rdx = i - l * WSZ;
    int m = rdx >> 12, r = rdx & 4095;
    const float* W  = l ? W2  : W1;
    const float* Wr = l ? Wr2 : Wr1;
    float v = (m < MKER) ? __ldg(W + (size_t)m * C * C + r) : __ldg(Wr + r);
    g_w16[i] = __float2half_rn(v);
}

// ---------------- transform via WMMA: 64-node tile x 4 m-planes --------------
// h tile staged ONCE per block (cuts redundant h traffic 28x -> 7x);
// per-m only the 8KB W plane is reloaded.
#define WM_NODES 64
#define HLD (C + 8)     // half smem leading dim (72; multiple of 8)
__global__ void __launch_bounds__(256)
transform_wmma_kernel(int N, int layer) {
    __shared__ __half hs[WM_NODES * HLD];   // [n][ci]   9216 B
    __shared__ __half ws[C * HLD];          // [ci][co]  9216 B
    __shared__ float  outs[WM_NODES * C];   // [n][co]  16384 B
    int mb  = blockIdx.y * 4;
    int n0  = blockIdx.x * WM_NODES;
    int tid = threadIdx.x;

    const __half* wbase = g_w16 + (size_t)layer * WSZ;

    // load h tile once
    for (int i = tid; i < WM_NODES * 8; i += 256) {
        int n = i >> 3, q = i & 7;
        uint4 v = make_uint4(0u, 0u, 0u, 0u);
        if (n0 + n < N)
            v = __ldg((const uint4*)(g_hh + (size_t)(n0 + n) * C) + q);
        *(uint4*)&hs[n * HLD + q * 8] = v;
    }

    int wid  = tid >> 5;
    int rowb = (wid >> 1) * 16;     // 0,16,32,48
    int colb = (wid & 1) * 32;      // 0,32
    int n  = tid >> 2, cq = (tid & 3) * 16;

    for (int it = 0; it < 4; it++) {
        int m = mb + it;
        // load W plane
        for (int i = tid; i < C * 8; i += 256) {
            int ci = i >> 3, q = i & 7;
            uint4 v = __ldg((const uint4*)(wbase + (size_t)m * C * C + ci * C) + q);
            *(uint4*)&ws[ci * HLD + q * 8] = v;
        }
        __syncthreads();

        wmma::fragment<wmma::accumulator, 16, 16, 16, float> cf0, cf1;
        wmma::fill_fragment(cf0, 0.f);
        wmma::fill_fragment(cf1, 0.f);
#pragma unroll
        for (int k = 0; k < 4; k++) {
            wmma::fragment<wmma::matrix_a, 16, 16, 16, __half, wmma::row_major> af;
            wmma::load_matrix_sync(af, &hs[rowb * HLD + k * 16], HLD);
            wmma::fragment<wmma::matrix_b, 16, 16, 16, __half, wmma::row_major> bf0, bf1;
            wmma::load_matrix_sync(bf0, &ws[(k * 16) * HLD + colb], HLD);
            wmma::load_matrix_sync(bf1, &ws[(k * 16) * HLD + colb + 16], HLD);
            wmma::mma_sync(cf0, af, bf0, cf0);
            wmma::mma_sync(cf1, af, bf1, cf1);
        }
        wmma::store_matrix_sync(&outs[rowb * C + colb],      cf0, C, wmma::mem_row_major);
        wmma::store_matrix_sync(&outs[rowb * C + colb + 16], cf1, C, wmma::mem_row_major);
        __syncthreads();

        // write out: thread t -> node t>>2, 16 channels at (t&3)*16
        if (n0 + n < N) {
            const float* row = &outs[n * C + cq];
            if (m < MKER) {
                __half2 buf[8];
#pragma unroll
                for (int j = 0; j < 8; j++)
                    buf[j] = __floats2half2_rn(row[2 * j], row[2 * j + 1]);
                uint4* dst = (uint4*)(g_y + (size_t)(n0 + n) * YSTR + m * C + cq);
                dst[0] = *(uint4*)&buf[0];
                dst[1] = *(uint4*)&buf[4];
            } else {
                float4* dst = (float4*)(g_root + (size_t)(n0 + n) * C + cq);
#pragma unroll
                for (int j = 0; j < 4; j++)
                    dst[j] = *(const float4*)&row[4 * j];
            }
        }
        __syncthreads();   // outs reused next iteration
    }
}

// ---------------- node kernel (layers 1,2): warp per dst node ----------------
__global__ void __launch_bounds__(256)
node_kernel(const float* __restrict__ bias, float* __restrict__ out32,
            int N, int writeFloat) {
    __shared__ float4 recs[8][32];
    int wid  = threadIdx.x >> 5;
    int lane = threadIdx.x & 31;
    int n    = (blockIdx.x * blockDim.x + threadIdx.x) >> 5;
    if (n >= N) return;
    int beg = g_rowptr[n], end = g_rowptr[n + 1];

    float2 acc = make_float2(0.f, 0.f);
    for (int base = beg; base < end; base += 32) {
        int cnt = min(32, end - base);
        __syncwarp();
        if (lane < cnt) recs[wid][lane] = __ldg(&g_rec[base + lane]);
        __syncwarp();
#pragma unroll 4
        for (int e = 0; e < cnt; e++) {
            float4 r = recs[wid][e];                 // LDS broadcast
            int s = __float_as_int(r.x);
            float w[8]; int kk[8];
            basis8(r.y, r.z, r.w, w, kk);
            const __half* yb = g_y + (size_t)s * YSTR;
#pragma unroll
            for (int c = 0; c < 8; c++) {
                __half2 hv = __ldg((const __half2*)(yb + kk[c] * C) + lane);
                float2 v = __half22float2(hv);
                acc.x += w[c] * v.x;
                acc.y += w[c] * v.y;
            }
        }
    }
    int   dg  = end - beg;
    float inv = 1.f / (float)(dg > 0 ? dg : 1);
    float2 rt = __ldg((const float2*)(g_root + (size_t)n * C) + lane);
    float2 bb = __ldg((const float2*)bias + lane);
    float v0 = fmaxf(acc.x * inv + rt.x + bb.x, 0.f);
    float v1 = fmaxf(acc.y * inv + rt.y + bb.y, 0.f);
    if (writeFloat) {
        ((float2*)out32)[(size_t)n * 32 + lane] = make_float2(v0, v1);
    } else {
        ((__half2*)g_hh)[(size_t)n * 32 + lane] = __floats2half2_rn(v0, v1);
    }
}

// ---------------- launch ----------------
extern "C" void kernel_launch(void* const* d_in, const int* in_sizes, int n_in,
                              void* d_out, int out_size) {
    const float* x     = (const float*)d_in[0];
    const int*   ei    = (const int*)d_in[1];
    const float* ea    = (const float*)d_in[2];
    const float* W0    = (const float*)d_in[3];
    const float* root0 = (const float*)d_in[4];
    const float* b0    = (const float*)d_in[5];
    const float* W1    = (const float*)d_in[6];
    const float* root1 = (const float*)d_in[7];
    const float* b1    = (const float*)d_in[8];
    const float* W2    = (const float*)d_in[9];
    const float* root2 = (const float*)d_in[10];
    const float* b2    = (const float*)d_in[11];
    float* out = (float*)d_out;

    int N = in_sizes[0] / 3;
    int E = in_sizes[1] / 2;
    const int* src = ei;
    const int* dst = ei + E;

    int nodeBlocks = (N * 32 + 255) / 256;
    dim3 tGrid((N + WM_NODES - 1) / WM_NODES, 7);     // 4 m-planes per block
    int wpBlocks = (2 * WSZ + 255) / 256;

    // ---- CSR + layer-0 scatter + weight prep (off critical path) ----
    zeroAll_kernel<<<(N * SSTR + 255) / 256, 256>>>(N);
    hist_kernel<<<(E + 255) / 256, 256>>>(dst, E);
    scan_kernel<<<1, 1024>>>(N);
    build_kernel<<<(E + 255) / 256, 256>>>(src, dst, ea, x, E);
    wprep_kernel<<<wpBlocks, 256>>>(W1, root1, W2, root2);

    // ---- layer 0 ----
    l0_kernel<<<nodeBlocks, 256>>>(x, W0, root0, b0, N);

    // ---- layer 1 ----
    transform_wmma_kernel<<<tGrid, 256>>>(N, 0);
    node_kernel<<<nodeBlocks, 256>>>(b1, nullptr, N, 0);

    // ---- layer 2 ----
    transform_wmma_kernel<<<tGrid, 256>>>(N, 1);
    node_kernel<<<nodeBlocks, 256>>>(b2, out, N, 1);
}

// round 16
// speedup vs baseline: 2.6503x; 1.1310x over previous
#include <cuda_runtime.h>
#include <cuda_fp16.h>
#include <mma.h>

using namespace nvcuda;

// ---------------- problem constants ----------------
#define NMAX 50000
#define EMAX 800000
#define MKER 27            // 3^3 spline kernels
#define C    64            // hidden channels
#define YSTR (MKER * C)    // 1728 halves per node
#define SSTR 108           // 27 * 4 (ci0,ci1,ci2,pad) layer-0 agg row
#define WSZ  (28 * C * C)  // 114688 halves per layer of prepped weights
#define SCB  64            // scan blocks

// ---------------- static scratch ----------------
__device__ __half g_y[(size_t)NMAX * YSTR];   // 172.8 MB transformed features (fp16)
__device__ __half g_hh[NMAX * C];             // hidden state (fp16)
__device__ __half g_w16[2 * WSZ];             // fp16 weights [layer][m][ci][co]
__device__ float  g_root[NMAX * C];           // fp32 root-weight term h @ Wr
__device__ float  g_S[NMAX * SSTR];           // layer-0 input-space agg (21.6 MB)
__device__ float4 g_rec[EMAX];                // CSR edge records: (src, ea0, ea1, ea2)
__device__ int    g_rowptr[NMAX + 1];
__device__ int    g_cursor[NMAX];
__device__ int    g_deg[NMAX];
__device__ int    g_part[SCB];

// ---------------- basis helpers ----------------
__device__ __forceinline__ void basis8(float e0, float e1, float e2,
                                       float w[8], int kk[8]) {
    float p0 = e0 * 2.0f, p1 = e1 * 2.0f, p2 = e2 * 2.0f;
    float f0 = fminf(fmaxf(floorf(p0), 0.f), 1.f);
    float f1 = fminf(fmaxf(floorf(p1), 0.f), 1.f);
    float f2 = fminf(fmaxf(floorf(p2), 0.f), 1.f);
    float u0 = p0 - f0, u1 = p1 - f1, u2 = p2 - f2;
    int base = (int)f0 + 3 * (int)f1 + 9 * (int)f2;
#pragma unroll
    for (int b = 0; b < 8; b++) {
        float a0 = (b & 1) ? u0 : 1.f - u0;
        float a1 = (b & 2) ? u1 : 1.f - u1;
        float a2 = (b & 4) ? u2 : 1.f - u2;
        w[b]  = a0 * a1 * a2;
        kk[b] = base + (b & 1) + 3 * ((b >> 1) & 1) + 9 * ((b >> 2) & 1);
    }
}

// ---------------- prepass ----------------
__global__ void zero4_kernel(int N) {
    int i = blockIdx.x * blockDim.x + threadIdx.x;
    if (i < N * (SSTR / 4))
        ((float4*)g_S)[i] = make_float4(0.f, 0.f, 0.f, 0.f);
    if (i < N) g_deg[i] = 0;
}
__global__ void hist_kernel(const int* __restrict__ dst, int E) {
    int i = blockIdx.x * blockDim.x + threadIdx.x;
    if (i < E) atomicAdd(&g_deg[dst[i]], 1);
}

// ---- parallel 3-stage scan of g_deg -> g_rowptr / g_cursor ----
__global__ void scanA_kernel(int N) {
    __shared__ int red[256];
    int b = blockIdx.x, t = threadIdx.x;
    int c1  = (N + SCB - 1) / SCB;
    int beg = b * c1, end = min(beg + c1, N);
    int s = 0;
    for (int i = beg + t; i < end; i += 256) s += g_deg[i];
    red[t] = s;
    __syncthreads();
    for (int o = 128; o > 0; o >>= 1) {
        if (t < o) red[t] += red[t + o];
        __syncthreads();
    }
    if (t == 0) g_part[b] = red[0];
}
__global__ void scanB_kernel(int N) {
    __shared__ int sp[SCB];
    int t = threadIdx.x;
    sp[t] = g_part[t];
    __syncthreads();
    for (int o = 1; o < SCB; o <<= 1) {
        int v = (t >= o) ? sp[t - o] : 0;
        __syncthreads();
        sp[t] += v;
        __syncthreads();
    }
    g_part[t] = (t == 0) ? 0 : sp[t - 1];      // exclusive
    if (t == SCB - 1) g_rowptr[N] = sp[SCB - 1];
}
__global__ void scanC_kernel(int N) {
    __shared__ int red[256];
    int b = blockIdx.x, t = threadIdx.x;
    int c1  = (N + SCB - 1) / SCB;
    int beg = b * c1, end = min(beg + c1, N);
    int c2  = (c1 + 255) / 256;
    int sb  = beg + t * c2, se = min(sb + c2, end);
    int s = 0;
    for (int i = sb; i < se; i++) s += g_deg[i];
    red[t] = s;
    __syncthreads();
    for (int o = 1; o < 256; o <<= 1) {         // inclusive scan
        int v = (t >= o) ? red[t - o] : 0;
        __syncthreads();
        red[t] += v;
        __syncthreads();
    }
    int run = g_part[b] + ((t == 0) ? 0 : red[t - 1]);
    for (int i = sb; i < se; i++) {
        g_rowptr[i] = run;
        g_cursor[i] = run;
        run += g_deg[i];
    }
}

__global__ void build_kernel(const int* __restrict__ src,
                             const int* __restrict__ dst,
                             const float* __restrict__ ea,
                             const float* __restrict__ x, int E) {
    int e = blockIdx.x * blockDim.x + threadIdx.x;
    if (e >= E) return;
    int s = src[e], d = dst[e];
    float e0 = ea[3 * e], e1 = ea[3 * e + 1], e2 = ea[3 * e + 2];

    int pos = atomicAdd(&g_cursor[d], 1);
    g_rec[pos] = make_float4(__int_as_float(s), e0, e1, e2);

    float w[8]; int kk[8];
    basis8(e0, e1, e2, w, kk);
    float x0 = __ldg(x + 3 * s), x1 = __ldg(x + 3 * s + 1), x2 = __ldg(x + 3 * s + 2);
    float4* Sb = (float4*)(g_S + (size_t)d * SSTR);
#pragma unroll
    for (int c = 0; c < 8; c++)
        atomicAdd(Sb + kk[c], make_float4(w[c] * x0, w[c] * x1, w[c] * x2, 0.f));
}

// ---------------- layer 0 finalize: h = relu(S@W0/deg + x@root0 + b0) --------
__global__ void __launch_bounds__(256)
l0_kernel(const float* __restrict__ x, const float* __restrict__ W0,
          const float* __restrict__ root0, const float* __restrict__ b0, int N) {
    int n    = (blockIdx.x * blockDim.x + threadIdx.x) >> 5;
    int lane = threadIdx.x & 31;
    if (n >= N) return;
    const float* Sr = g_S + (size_t)n * SSTR;
    float sA = Sr[lane];
    float sB = Sr[32 + lane];
    float sC = Sr[64 + lane];
    float sD = (lane < 12) ? Sr[96 + lane] : 0.f;

    float2 acc = make_float2(0.f, 0.f);
#pragma unroll
    for (int m = 0; m < MKER; m++) {
#pragma unroll
        for (int ci = 0; ci < 3; ci++) {
            int s  = m * 4 + ci;
            int r  = s >> 5, sl = s & 31;
            float v = (r == 0) ? __shfl_sync(0xffffffffu, sA, sl)
                    : (r == 1) ? __shfl_sync(0xffffffffu, sB, sl)
                    : (r == 2) ? __shfl_sync(0xffffffffu, sC, sl)
                               : __shfl_sync(0xffffffffu, sD, sl);
            float2 wv = __ldg((const float2*)(W0 + (m * 3 + ci) * C) + lane);
            acc.x += v * wv.x;
            acc.y += v * wv.y;
        }
    }
    int   dg  = g_rowptr[n + 1] - g_rowptr[n];
    float inv = 1.f / (float)(dg > 0 ? dg : 1);
    float xv  = (lane < 3) ? __ldg(x + 3 * n + lane) : 0.f;
    float x0  = __shfl_sync(0xffffffffu, xv, 0);
    float x1  = __shfl_sync(0xffffffffu, xv, 1);
    float x2  = __shfl_sync(0xffffffffu, xv, 2);
    float2 r0 = __ldg((const float2*)(root0)         + lane);
    float2 r1 = __ldg((const float2*)(root0 + C)     + lane);
    float2 r2 = __ldg((const float2*)(root0 + 2 * C) + lane);
    float2 bb = __ldg((const float2*)(b0)            + lane);
    float v0 = fmaxf(acc.x * inv + x0 * r0.x + x1 * r1.x + x2 * r2.x + bb.x, 0.f);
    float v1 = fmaxf(acc.y * inv + x0 * r0.y + x1 * r1.y + x2 * r2.y + bb.y, 0.f);
    ((__half2*)g_hh)[(size_t)n * 32 + lane] = __floats2half2_rn(v0, v1);
}

// ---------------- W prep (both layers at once): g_w16[l][m][ci][co] ----------
__global__ void wprep_kernel(const float* __restrict__ W1,
                             const float* __restrict__ Wr1,
                             const float* __restrict__ W2,
                             const float* __restrict__ Wr2) {
    int i = blockIdx.x * blockDim.x + threadIdx.x;
    if (i >= 2 * WSZ) return;
    int l   = i / WSZ;
    int rdx = i - l * WSZ;
    int m = rdx >> 12, r = rdx & 4095;
    const float* W  = l ? W2  : W1;
    const float* Wr = l ? Wr2 : Wr1;
    float v = (m < MKER) ? __ldg(W + (size_t)m * C * C + r) : __ldg(Wr + r);
    g_w16[i] = __float2half_rn(v);
}

// ---------------- transform via WMMA: 64-node tile x 7 m-planes --------------
// h staged once per block; W double-buffered in smem with register prefetch:
// 2 syncs per plane, W-load latency hidden behind MMA + writeout.
#define WM_NODES 64
#define HLD (C + 8)     // half smem leading dim (72)
__global__ void __launch_bounds__(256)
transform_wmma_kernel(int N, int layer) {
    __shared__ __half hs[WM_NODES * HLD];     //  9216 B
    __shared__ __half ws[2][C * HLD];         // 18432 B (double buffer)
    __shared__ float  outs[WM_NODES * C];     // 16384 B
    int mb  = blockIdx.y * 7;
    int n0  = blockIdx.x * WM_NODES;
    int tid = threadIdx.x;

    const __half* wbase = g_w16 + (size_t)layer * WSZ;

    // load h tile once
    for (int i = tid; i < WM_NODES * 8; i += 256) {
        int n = i >> 3, q = i & 7;
        uint4 v = make_uint4(0u, 0u, 0u, 0u);
        if (n0 + n < N)
            v = __ldg((const uint4*)(g_hh + (size_t)(n0 + n) * C) + q);
        *(uint4*)&hs[n * HLD + q * 8] = v;
    }

    // W plane = 512 uint4; this thread owns indices i0, i1. src offset = i*8 halves.
    int i0 = tid, i1 = tid + 256;
    // prologue: plane mb -> ws[0]
    {
        const uint4* wp = (const uint4*)(wbase + (size_t)mb * C * C);
        uint4 a = __ldg(wp + i0);
        uint4 b = __ldg(wp + i1);
        *(uint4*)&ws[0][(i0 >> 3) * HLD + (i0 & 7) * 8] = a;
        *(uint4*)&ws[0][(i1 >> 3) * HLD + (i1 & 7) * 8] = b;
    }
    __syncthreads();

    int wid  = tid >> 5;
    int rowb = (wid >> 1) * 16;     // 0,16,32,48
    int colb = (wid & 1) * 32;      // 0,32
    int n  = tid >> 2, cq = (tid & 3) * 16;

    for (int it = 0; it < 7; it++) {
        int m   = mb + it;
        int buf = it & 1;

        // prefetch next W plane into registers (overlaps MMA)
        uint4 pa = make_uint4(0u,0u,0u,0u), pb = make_uint4(0u,0u,0u,0u);
        if (it < 6) {
            const uint4* wp = (const uint4*)(wbase + (size_t)(m + 1) * C * C);
            pa = __ldg(wp + i0);
            pb = __ldg(wp + i1);
        }

        wmma::fragment<wmma::accumulator, 16, 16, 16, float> cf0, cf1;
        wmma::fill_fragment(cf0, 0.f);
        wmma::fill_fragment(cf1, 0.f);
#pragma unroll
        for (int k = 0; k < 4; k++) {
            wmma::fragment<wmma::matrix_a, 16, 16, 16, __half, wmma::row_major> af;
            wmma::load_matrix_sync(af, &hs[rowb * HLD + k * 16], HLD);
            wmma::fragment<wmma::matrix_b, 16, 16, 16, __half, wmma::row_major> bf0, bf1;
            wmma::load_matrix_sync(bf0, &ws[buf][(k * 16) * HLD + colb], HLD);
            wmma::load_matrix_sync(bf1, &ws[buf][(k * 16) * HLD + colb + 16], HLD);
            wmma::mma_sync(cf0, af, bf0, cf0);
            wmma::mma_sync(cf1, af, bf1, cf1);
        }
        wmma::store_matrix_sync(&outs[rowb * C + colb],      cf0, C, wmma::mem_row_major);
        wmma::store_matrix_sync(&outs[rowb * C + colb + 16], cf1, C, wmma::mem_row_major);
        __syncthreads();                       // outs ready; ws[buf] reads done

        // fill next W buffer + writeout current plane
        if (it < 6) {
            *(uint4*)&ws[buf ^ 1][(i0 >> 3) * HLD + (i0 & 7) * 8] = pa;
            *(uint4*)&ws[buf ^ 1][(i1 >> 3) * HLD + (i1 & 7) * 8] = pb;
        }
        if (n0 + n < N) {
            const float* row = &outs[n * C + cq];
            if (m < MKER) {
                __half2 bufh[8];
#pragma unroll
                for (int j = 0; j < 8; j++)
                    bufh[j] = __floats2half2_rn(row[2 * j], row[2 * j + 1]);
                uint4* dst = (uint4*)(g_y + (size_t)(n0 + n) * YSTR + m * C + cq);
                dst[0] = *(uint4*)&bufh[0];
                dst[1] = *(uint4*)&bufh[4];
            } else {
                float4* dst = (float4*)(g_root + (size_t)(n0 + n) * C + cq);
#pragma unroll
                for (int j = 0; j < 4; j++)
                    dst[j] = *(const float4*)&row[4 * j];
            }
        }
        __syncthreads();                       // outs free; ws[buf^1] ready
    }
}

// ---------------- node kernel (layers 1,2): warp per dst node ----------------
__global__ void __launch_bounds__(256)
node_kernel(const float* __restrict__ bias, float* __restrict__ out32,
            int N, int writeFloat) {
    __shared__ float4 recs[8][32];
    int wid  = threadIdx.x >> 5;
    int lane = threadIdx.x & 31;
    int n    = (blockIdx.x * blockDim.x + threadIdx.x) >> 5;
    if (n >= N) return;
    int beg = g_rowptr[n], end = g_rowptr[n + 1];

    float2 acc = make_float2(0.f, 0.f);
    for (int base = beg; base < end; base += 32) {
        int cnt = min(32, end - base);
        __syncwarp();
        if (lane < cnt) recs[wid][lane] = __ldg(&g_rec[base + lane]);
        __syncwarp();
#pragma unroll 4
        for (int e = 0; e < cnt; e++) {
            float4 r = recs[wid][e];                 // LDS broadcast
            int s = __float_as_int(r.x);
            float w[8]; int kk[8];
            basis8(r.y, r.z, r.w, w, kk);
            const __half* yb = g_y + (size_t)s * YSTR;
#pragma unroll
            for (int c = 0; c < 8; c++) {
                __half2 hv = __ldg((const __half2*)(yb + kk[c] * C) + lane);
                float2 v = __half22float2(hv);
                acc.x += w[c] * v.x;
                acc.y += w[c] * v.y;
            }
        }
    }
    int   dg  = end - beg;
    float inv = 1.f / (float)(dg > 0 ? dg : 1);
    float2 rt = __ldg((const float2*)(g_root + (size_t)n * C) + lane);
    float2 bb = __ldg((const float2*)bias + lane);
    float v0 = fmaxf(acc.x * inv + rt.x + bb.x, 0.f);
    float v1 = fmaxf(acc.y * inv + rt.y + bb.y, 0.f);
    if (writeFloat) {
        ((float2*)out32)[(size_t)n * 32 + lane] = make_float2(v0, v1);
    } else {
        ((__half2*)g_hh)[(size_t)n * 32 + lane] = __floats2half2_rn(v0, v1);
    }
}

// ---------------- launch ----------------
extern "C" void kernel_launch(void* const* d_in, const int* in_sizes, int n_in,
                              void* d_out, int out_size) {
    const float* x     = (const float*)d_in[0];
    const int*   ei    = (const int*)d_in[1];
    const float* ea    = (const float*)d_in[2];
    const float* W0    = (const float*)d_in[3];
    const float* root0 = (const float*)d_in[4];
    const float* b0    = (const float*)d_in[5];
    const float* W1    = (const float*)d_in[6];
    const float* root1 = (const float*)d_in[7];
    const float* b1    = (const float*)d_in[8];
    const float* W2    = (const float*)d_in[9];
    const float* root2 = (const float*)d_in[10];
    const float* b2    = (const float*)d_in[11];
    float* out = (float*)d_out;

    int N = in_sizes[0] / 3;
    int E = in_sizes[1] / 2;
    const int* src = ei;
    const int* dst = ei + E;

    int nodeBlocks = (N * 32 + 255) / 256;
    dim3 tGrid((N + WM_NODES - 1) / WM_NODES, 4);     // 7 m-planes per block
    int wpBlocks = (2 * WSZ + 255) / 256;

    // ---- CSR + layer-0 scatter + weight prep ----
    zero4_kernel<<<(N * (SSTR / 4) + 255) / 256, 256>>>(N);
    hist_kernel<<<(E + 255) / 256, 256>>>(dst, E);
    scanA_kernel<<<SCB, 256>>>(N);
    scanB_kernel<<<1, SCB>>>(N);
    scanC_kernel<<<SCB, 256>>>(N);
    build_kernel<<<(E + 255) / 256, 256>>>(src, dst, ea, x, E);
    wprep_kernel<<<wpBlocks, 256>>>(W1, root1, W2, root2);

    // ---- layer 0 ----
    l0_kernel<<<nodeBlocks, 256>>>(x, W0, root0, b0, N);

    // ---- layer 1 ----
    transform_wmma_kernel<<<tGrid, 256>>>(N, 0);
    node_kernel<<<nodeBlocks, 256>>>(b1, nullptr, N, 0);

    // ---- layer 2 ----
    transform_wmma_kernel<<<tGrid, 256>>>(N, 1);
    node_kernel<<<nodeBlocks, 256>>>(b2, out, N, 1);
}

// round 17
// speedup vs baseline: 2.6559x; 1.0021x over previous
#include <cuda_runtime.h>
#include <cuda_fp16.h>
#include <mma.h>

using namespace nvcuda;

// ---------------- problem constants ----------------
#define NMAX 50000
#define EMAX 800000
#define MKER 27            // 3^3 spline kernels
#define C    64            // hidden channels
#define YSTR (MKER * C)    // 1728 halves per node
#define SSTR 108           // 27 * 4 (ci0,ci1,ci2,pad) layer-0 agg row
#define WSZ  (28 * C * C)  // 114688 halves per layer of prepped weights
#define SCB  64            // scan blocks

// ---------------- static scratch ----------------
__device__ __half g_y[(size_t)NMAX * YSTR];   // 172.8 MB transformed features (fp16)
__device__ __half g_hh[NMAX * C];             // hidden state (fp16)
__device__ __half g_w16[2 * WSZ];             // fp16 weights [layer][m][ci][co]
__device__ float  g_root[NMAX * C];           // fp32 root-weight term h @ Wr
__device__ float  g_S[NMAX * SSTR];           // layer-0 input-space agg (21.6 MB)
__device__ uint4  g_wrec[EMAX];               // per-edge 8 fp16 basis weights
__device__ unsigned g_mrec[EMAX];             // per-edge meta: src | base<<28
__device__ int    g_rowptr[NMAX + 1];
__device__ int    g_cursor[NMAX];
__device__ int    g_deg[NMAX];
__device__ int    g_part[SCB];

// ---------------- basis helpers ----------------
__device__ __forceinline__ void basis8(float e0, float e1, float e2,
                                       float w[8], int kk[8], int& base) {
    float p0 = e0 * 2.0f, p1 = e1 * 2.0f, p2 = e2 * 2.0f;
    float f0 = fminf(fmaxf(floorf(p0), 0.f), 1.f);
    float f1 = fminf(fmaxf(floorf(p1), 0.f), 1.f);
    float f2 = fminf(fmaxf(floorf(p2), 0.f), 1.f);
    float u0 = p0 - f0, u1 = p1 - f1, u2 = p2 - f2;
    base = (int)f0 + 3 * (int)f1 + 9 * (int)f2;
#pragma unroll
    for (int b = 0; b < 8; b++) {
        float a0 = (b & 1) ? u0 : 1.f - u0;
        float a1 = (b & 2) ? u1 : 1.f - u1;
        float a2 = (b & 4) ? u2 : 1.f - u2;
        w[b]  = a0 * a1 * a2;
        kk[b] = base + (b & 1) + 3 * ((b >> 1) & 1) + 9 * ((b >> 2) & 1);
    }
}

// ---------------- prepass ----------------
__global__ void zero4_kernel(int N) {
    int i = blockIdx.x * blockDim.x + threadIdx.x;
    if (i < N * (SSTR / 4))
        ((float4*)g_S)[i] = make_float4(0.f, 0.f, 0.f, 0.f);
    if (i < N) g_deg[i] = 0;
}
__global__ void hist_kernel(const int* __restrict__ dst, int E) {
    int i = blockIdx.x * blockDim.x + threadIdx.x;
    if (i < E) atomicAdd(&g_deg[dst[i]], 1);
}

// ---- parallel 3-stage scan of g_deg -> g_rowptr / g_cursor ----
__global__ void scanA_kernel(int N) {
    __shared__ int red[256];
    int b = blockIdx.x, t = threadIdx.x;
    int c1  = (N + SCB - 1) / SCB;
    int beg = b * c1, end = min(beg + c1, N);
    int s = 0;
    for (int i = beg + t; i < end; i += 256) s += g_deg[i];
    red[t] = s;
    __syncthreads();
    for (int o = 128; o > 0; o >>= 1) {
        if (t < o) red[t] += red[t + o];
        __syncthreads();
    }
    if (t == 0) g_part[b] = red[0];
}
__global__ void scanB_kernel(int N) {
    __shared__ int sp[SCB];
    int t = threadIdx.x;
    sp[t] = g_part[t];
    __syncthreads();
    for (int o = 1; o < SCB; o <<= 1) {
        int v = (t >= o) ? sp[t - o] : 0;
        __syncthreads();
        sp[t] += v;
        __syncthreads();
    }
    g_part[t] = (t == 0) ? 0 : sp[t - 1];      // exclusive
    if (t == SCB - 1) g_rowptr[N] = sp[SCB - 1];
}
__global__ void scanC_kernel(int N) {
    __shared__ int red[256];
    int b = blockIdx.x, t = threadIdx.x;
    int c1  = (N + SCB - 1) / SCB;
    int beg = b * c1, end = min(beg + c1, N);
    int c2  = (c1 + 255) / 256;
    int sb  = beg + t * c2, se = min(sb + c2, end);
    int s = 0;
    for (int i = sb; i < se; i++) s += g_deg[i];
    red[t] = s;
    __syncthreads();
    for (int o = 1; o < 256; o <<= 1) {         // inclusive scan
        int v = (t >= o) ? red[t - o] : 0;
        __syncthreads();
        red[t] += v;
        __syncthreads();
    }
    int run = g_part[b] + ((t == 0) ? 0 : red[t - 1]);
    for (int i = sb; i < se; i++) {
        g_rowptr[i] = run;
        g_cursor[i] = run;
        run += g_deg[i];
    }
}

// edge pass: basis precompute + CSR placement + layer-0 input-space scatter
__global__ void build_kernel(const int* __restrict__ src,
                             const int* __restrict__ dst,
                             const float* __restrict__ ea,
                             const float* __restrict__ x, int E) {
    int e = blockIdx.x * blockDim.x + threadIdx.x;
    if (e >= E) return;
    int s = src[e], d = dst[e];
    float e0 = ea[3 * e], e1 = ea[3 * e + 1], e2 = ea[3 * e + 2];

    float w[8]; int kk[8]; int base;
    basis8(e0, e1, e2, w, kk, base);

    int pos = atomicAdd(&g_cursor[d], 1);
    g_mrec[pos] = (unsigned)s | ((unsigned)base << 28);
    uint4 wq;
    __half2 p01 = __floats2half2_rn(w[0], w[1]);
    __half2 p23 = __floats2half2_rn(w[2], w[3]);
    __half2 p45 = __floats2half2_rn(w[4], w[5]);
    __half2 p67 = __floats2half2_rn(w[6], w[7]);
    wq.x = *reinterpret_cast<unsigned*>(&p01);
    wq.y = *reinterpret_cast<unsigned*>(&p23);
    wq.z = *reinterpret_cast<unsigned*>(&p45);
    wq.w = *reinterpret_cast<unsigned*>(&p67);
    g_wrec[pos] = wq;

    float x0 = __ldg(x + 3 * s), x1 = __ldg(x + 3 * s + 1), x2 = __ldg(x + 3 * s + 2);
    float4* Sb = (float4*)(g_S + (size_t)d * SSTR);
#pragma unroll
    for (int c = 0; c < 8; c++)
        atomicAdd(Sb + kk[c], make_float4(w[c] * x0, w[c] * x1, w[c] * x2, 0.f));
}

// ---------------- layer 0 finalize: h = relu(S@W0/deg + x@root0 + b0) --------
__global__ void __launch_bounds__(256)
l0_kernel(const float* __restrict__ x, const float* __restrict__ W0,
          const float* __restrict__ root0, const float* __restrict__ b0, int N) {
    int n    = (blockIdx.x * blockDim.x + threadIdx.x) >> 5;
    int lane = threadIdx.x & 31;
    if (n >= N) return;
    const float* Sr = g_S + (size_t)n * SSTR;
    float sA = Sr[lane];
    float sB = Sr[32 + lane];
    float sC = Sr[64 + lane];
    float sD = (lane < 12) ? Sr[96 + lane] : 0.f;

    float2 acc = make_float2(0.f, 0.f);
#pragma unroll
    for (int m = 0; m < MKER; m++) {
#pragma unroll
        for (int ci = 0; ci < 3; ci++) {
            int s  = m * 4 + ci;
            int r  = s >> 5, sl = s & 31;
            float v = (r == 0) ? __shfl_sync(0xffffffffu, sA, sl)
                    : (r == 1) ? __shfl_sync(0xffffffffu, sB, sl)
                    : (r == 2) ? __shfl_sync(0xffffffffu, sC, sl)
                               : __shfl_sync(0xffffffffu, sD, sl);
            float2 wv = __ldg((const float2*)(W0 + (m * 3 + ci) * C) + lane);
            acc.x += v * wv.x;
            acc.y += v * wv.y;
        }
    }
    int   dg  = g_rowptr[n + 1] - g_rowptr[n];
    float inv = 1.f / (float)(dg > 0 ? dg : 1);
    float xv  = (lane < 3) ? __ldg(x + 3 * n + lane) : 0.f;
    float x0  = __shfl_sync(0xffffffffu, xv, 0);
    float x1  = __shfl_sync(0xffffffffu, xv, 1);
    float x2  = __shfl_sync(0xffffffffu, xv, 2);
    float2 r0 = __ldg((const float2*)(root0)         + lane);
    float2 r1 = __ldg((const float2*)(root0 + C)     + lane);
    float2 r2 = __ldg((const float2*)(root0 + 2 * C) + lane);
    float2 bb = __ldg((const float2*)(b0)            + lane);
    float v0 = fmaxf(acc.x * inv + x0 * r0.x + x1 * r1.x + x2 * r2.x + bb.x, 0.f);
    float v1 = fmaxf(acc.y * inv + x0 * r0.y + x1 * r1.y + x2 * r2.y + bb.y, 0.f);
    ((__half2*)g_hh)[(size_t)n * 32 + lane] = __floats2half2_rn(v0, v1);
}

// ---------------- W prep (both layers at once): g_w16[l][m][ci][co] ----------
__global__ void wprep_kernel(const float* __restrict__ W1,
                             const float* __restrict__ Wr1,
                             const float* __restrict__ W2,
                             const float* __restrict__ Wr2) {
    int i = blockIdx.x * blockDim.x + threadIdx.x;
    if (i >= 2 * WSZ) return;
    int l   = i / WSZ;
    int rdx = i - l * WSZ;
    int m = rdx >> 12, r = rdx & 4095;
    const float* W  = l ? W2  : W1;
    const float* Wr = l ? Wr2 : Wr1;
    float v = (m < MKER) ? __ldg(W + (size_t)m * C * C + r) : __ldg(Wr + r);
    g_w16[i] = __float2half_rn(v);
}

// ---------------- transform via WMMA: 64-node tile x 7 m-planes --------------
#define WM_NODES 64
#define HLD (C + 8)     // half smem leading dim (72)
__global__ void __launch_bounds__(256)
transform_wmma_kernel(int N, int layer) {
    __shared__ __half hs[WM_NODES * HLD];     //  9216 B
    __shared__ __half ws[2][C * HLD];         // 18432 B (double buffer)
    __shared__ float  outs[WM_NODES * C];     // 16384 B
    int mb  = blockIdx.y * 7;
    int n0  = blockIdx.x * WM_NODES;
    int tid = threadIdx.x;

    const __half* wbase = g_w16 + (size_t)layer * WSZ;

    for (int i = tid; i < WM_NODES * 8; i += 256) {
        int n = i >> 3, q = i & 7;
        uint4 v = make_uint4(0u, 0u, 0u, 0u);
        if (n0 + n < N)
            v = __ldg((const uint4*)(g_hh + (size_t)(n0 + n) * C) + q);
        *(uint4*)&hs[n * HLD + q * 8] = v;
    }

    int i0 = tid, i1 = tid + 256;
    {
        const uint4* wp = (const uint4*)(wbase + (size_t)mb * C * C);
        uint4 a = __ldg(wp + i0);
        uint4 b = __ldg(wp + i1);
        *(uint4*)&ws[0][(i0 >> 3) * HLD + (i0 & 7) * 8] = a;
        *(uint4*)&ws[0][(i1 >> 3) * HLD + (i1 & 7) * 8] = b;
    }
    __syncthreads();

    int wid  = tid >> 5;
    int rowb = (wid >> 1) * 16;
    int colb = (wid & 1) * 32;
    int n  = tid >> 2, cq = (tid & 3) * 16;

    for (int it = 0; it < 7; it++) {
        int m   = mb + it;
        int buf = it & 1;

        uint4 pa = make_uint4(0u,0u,0u,0u), pb = make_uint4(0u,0u,0u,0u);
        if (it < 6) {
            const uint4* wp = (const uint4*)(wbase + (size_t)(m + 1) * C * C);
            pa = __ldg(wp + i0);
            pb = __ldg(wp + i1);
        }

        wmma::fragment<wmma::accumulator, 16, 16, 16, float> cf0, cf1;
        wmma::fill_fragment(cf0, 0.f);
        wmma::fill_fragment(cf1, 0.f);
#pragma unroll
        for (int k = 0; k < 4; k++) {
            wmma::fragment<wmma::matrix_a, 16, 16, 16, __half, wmma::row_major> af;
            wmma::load_matrix_sync(af, &hs[rowb * HLD + k * 16], HLD);
            wmma::fragment<wmma::matrix_b, 16, 16, 16, __half, wmma::row_major> bf0, bf1;
            wmma::load_matrix_sync(bf0, &ws[buf][(k * 16) * HLD + colb], HLD);
            wmma::load_matrix_sync(bf1, &ws[buf][(k * 16) * HLD + colb + 16], HLD);
            wmma::mma_sync(cf0, af, bf0, cf0);
            wmma::mma_sync(cf1, af, bf1, cf1);
        }
        wmma::store_matrix_sync(&outs[rowb * C + colb],      cf0, C, wmma::mem_row_major);
        wmma::store_matrix_sync(&outs[rowb * C + colb + 16], cf1, C, wmma::mem_row_major);
        __syncthreads();

        if (it < 6) {
            *(uint4*)&ws[buf ^ 1][(i0 >> 3) * HLD + (i0 & 7) * 8] = pa;
            *(uint4*)&ws[buf ^ 1][(i1 >> 3) * HLD + (i1 & 7) * 8] = pb;
        }
        if (n0 + n < N) {
            const float* row = &outs[n * C + cq];
            if (m < MKER) {
                __half2 bufh[8];
#pragma unroll
                for (int j = 0; j < 8; j++)
                    bufh[j] = __floats2half2_rn(row[2 * j], row[2 * j + 1]);
                uint4* dst = (uint4*)(g_y + (size_t)(n0 + n) * YSTR + m * C + cq);
                dst[0] = *(uint4*)&bufh[0];
                dst[1] = *(uint4*)&bufh[4];
            } else {
                float4* dst = (float4*)(g_root + (size_t)(n0 + n) * C + cq);
#pragma unroll
                for (int j = 0; j < 4; j++)
                    dst[j] = *(const float4*)&row[4 * j];
            }
        }
        __syncthreads();
    }
}

// ---------------- node kernel: precomputed basis, static corner offsets ------
__global__ void __launch_bounds__(256)
node_kernel(const float* __restrict__ bias, float* __restrict__ out32,
            int N, int writeFloat) {
    __shared__ uint4    wrecs[8][32];
    __shared__ unsigned mrecs[8][32];
    int wid  = threadIdx.x >> 5;
    int lane = threadIdx.x & 31;
    int n    = (blockIdx.x * blockDim.x + threadIdx.x) >> 5;
    if (n >= N) return;
    int beg = g_rowptr[n], end = g_rowptr[n + 1];

    // static corner offsets (in halves): {0,1,3,4,9,10,12,13} * C
    const int off0 = 0 * C,  off1 = 1 * C,  off2 = 3 * C,  off3 = 4 * C;
    const int off4 = 9 * C,  off5 = 10 * C, off6 = 12 * C, off7 = 13 * C;

    float2 acc = make_float2(0.f, 0.f);
    for (int bb = beg; bb < end; bb += 32) {
        int cnt = min(32, end - bb);
        __syncwarp();
        if (lane < cnt) {
            wrecs[wid][lane] = __ldg(&g_wrec[bb + lane]);
            mrecs[wid][lane] = __ldg(&g_mrec[bb + lane]);
        }
        __syncwarp();
#pragma unroll 4
        for (int e = 0; e < cnt; e++) {
            unsigned meta = mrecs[wid][e];
            uint4    wq   = wrecs[wid][e];
            int s    = (int)(meta & 0x0FFFFFFFu);
            int base = (int)(meta >> 28);
            float2 w01 = __half22float2(*reinterpret_cast<__half2*>(&wq.x));
            float2 w23 = __half22float2(*reinterpret_cast<__half2*>(&wq.y));
            float2 w45 = __half22float2(*reinterpret_cast<__half2*>(&wq.z));
            float2 w67 = __half22float2(*reinterpret_cast<__half2*>(&wq.w));
            const __half* yb = g_y + (size_t)s * YSTR + base * C;
            float2 v;
            v = __half22float2(__ldg((const __half2*)(yb + off0) + lane));
            acc.x += w01.x * v.x; acc.y += w01.x * v.y;
            v = __half22float2(__ldg((const __half2*)(yb + off1) + lane));
            acc.x += w01.y * v.x; acc.y += w01.y * v.y;
            v = __half22float2(__ldg((const __half2*)(yb + off2) + lane));
            acc.x += w23.x * v.x; acc.y += w23.x * v.y;
            v = __half22float2(__ldg((const __half2*)(yb + off3) + lane));
            acc.x += w23.y * v.x; acc.y += w23.y * v.y;
            v = __half22float2(__ldg((const __half2*)(yb + off4) + lane));
            acc.x += w45.x * v.x; acc.y += w45.x * v.y;
            v = __half22float2(__ldg((const __half2*)(yb + off5) + lane));
            acc.x += w45.y * v.x; acc.y += w45.y * v.y;
            v = __half22float2(__ldg((const __half2*)(yb + off6) + lane));
            acc.x += w67.x * v.x; acc.y += w67.x * v.y;
            v = __half22float2(__ldg((const __half2*)(yb + off7) + lane));
            acc.x += w67.y * v.x; acc.y += w67.y * v.y;
        }
    }
    int   dg  = end - beg;
    float inv = 1.f / (float)(dg > 0 ? dg : 1);
    float2 rt = __ldg((const float2*)(g_root + (size_t)n * C) + lane);
    float2 bv = __ldg((const float2*)bias + lane);
    float v0 = fmaxf(acc.x * inv + rt.x + bv.x, 0.f);
    float v1 = fmaxf(acc.y * inv + rt.y + bv.y, 0.f);
    if (writeFloat) {
        ((float2*)out32)[(size_t)n * 32 + lane] = make_float2(v0, v1);
    } else {
        ((__half2*)g_hh)[(size_t)n * 32 + lane] = __floats2half2_rn(v0, v1);
    }
}

// ---------------- launch ----------------
extern "C" void kernel_launch(void* const* d_in, const int* in_sizes, int n_in,
                              void* d_out, int out_size) {
    const float* x     = (const float*)d_in[0];
    const int*   ei    = (const int*)d_in[1];
    const float* ea    = (const float*)d_in[2];
    const float* W0    = (const float*)d_in[3];
    const float* root0 = (const float*)d_in[4];
    const float* b0    = (const float*)d_in[5];
    const float* W1    = (const float*)d_in[6];
    const float* root1 = (const float*)d_in[7];
    const float* b1    = (const float*)d_in[8];
    const float* W2    = (const float*)d_in[9];
    const float* root2 = (const float*)d_in[10];
    const float* b2    = (const float*)d_in[11];
    float* out = (float*)d_out;

    int N = in_sizes[0] / 3;
    int E = in_sizes[1] / 2;
    const int* src = ei;
    const int* dst = ei + E;

    int nodeBlocks = (N * 32 + 255) / 256;
    dim3 tGrid((N + WM_NODES - 1) / WM_NODES, 4);     // 7 m-planes per block
    int wpBlocks = (2 * WSZ + 255) / 256;

    // ---- CSR + basis precompute + layer-0 scatter + weight prep ----
    zero4_kernel<<<(N * (SSTR / 4) + 255) / 256, 256>>>(N);
    hist_kernel<<<(E + 255) / 256, 256>>>(dst, E);
    scanA_kernel<<<SCB, 256>>>(N);
    scanB_kernel<<<1, SCB>>>(N);
    scanC_kernel<<<SCB, 256>>>(N);
    build_kernel<<<(E + 255) / 256, 256>>>(src, dst, ea, x, E);
    wprep_kernel<<<wpBlocks, 256>>>(W1, root1, W2, root2);

    // ---- layer 0 ----
    l0_kernel<<<nodeBlocks, 256>>>(x, W0, root0, b0, N);

    // ---- layer 1 ----
    transform_wmma_kernel<<<tGrid, 256>>>(N, 0);
    node_kernel<<<nodeBlocks, 256>>>(b1, nullptr, N, 0);

    // ---- layer 2 ----
    transform_wmma_kernel<<<tGrid, 256>>>(N, 1);
    node_kernel<<<nodeBlocks, 256>>>(b2, out, N, 1);
}